// round 1
// baseline (speedup 1.0000x reference)
#include <cuda_runtime.h>
#include <cuda_bf16.h>

#define KDIM 64

// ---- packed f32x2 helpers (sm_100+) ----
__device__ __forceinline__ unsigned long long pk2(float a, float b) {
    unsigned long long r;
    asm("mov.b64 %0, {%1, %2};" : "=l"(r) : "f"(a), "f"(b));
    return r;
}
__device__ __forceinline__ unsigned long long fma2(unsigned long long a, unsigned long long b,
                                                   unsigned long long c) {
    unsigned long long d;
    asm("fma.rn.f32x2 %0, %1, %2, %3;" : "=l"(d) : "l"(a), "l"(b), "l"(c));
    return d;
}
__device__ __forceinline__ unsigned long long add2(unsigned long long a, unsigned long long b) {
    unsigned long long d;
    asm("add.rn.f32x2 %0, %1, %2;" : "=l"(d) : "l"(a), "l"(b));
    return d;
}

// One CTA per batch row b. Thread j owns CRF state j.
// alpha represented as C (scalar, uniform across threads) + r_j (per-thread residual).
// Forward step in exp domain: alpha_new[j] = C + ln( sum_i exp(r_i) * E[i][j] ) + emit[j],
// with E[i][j] = exp(trans[i][j]) held in registers (column j per thread, packed pairs).
__global__ __launch_bounds__(KDIM, 6) void crf_fwd_kernel(
    const float* __restrict__ y_pred,   // [B, N, K]
    const float* __restrict__ trans,    // [K, K]
    const int*   __restrict__ y_true,   // [B, N]
    float*       __restrict__ out,      // [B]
    int N)
{
    __shared__ float sh_trans[KDIM * KDIM];
    __shared__ __align__(16) float sh_e[KDIM];
    __shared__ float sh_red[KDIM];
    __shared__ float sh_delta;

    const int j = threadIdx.x;
    const int b = blockIdx.x;

    // Load trans (16 KB) into shared; all blocks hit L2 after the first wave.
    for (int i = j; i < KDIM * KDIM; i += KDIM) sh_trans[i] = trans[i];
    __syncthreads();

    // Column j of E = exp(trans), packed as 32 x f32x2 register pairs.
    unsigned long long Ec[KDIM / 2];
#pragma unroll
    for (int k = 0; k < KDIM / 2; ++k) {
        float e0 = __expf(sh_trans[(2 * k)     * KDIM + j]);
        float e1 = __expf(sh_trans[(2 * k + 1) * KDIM + j]);
        Ec[k] = pk2(e0, e1);
    }

    const float* yrow = y_pred + (size_t)b * N * KDIM;
    const int*   trow = y_true + (size_t)b * N;

    // ---- t = 0: init ----
    float yv = yrow[j];
    int   yt = trow[0];
    int   m  = __syncthreads_and(yv > -1000000.0f);   // mask[b,0]; also a barrier
    float fm = m ? 1.0f : 0.0f;
    float x  = yv * fm;                                // init alpha_j (masked emit)
    float point = (j == yt) ? x : 0.0f;                // point term at t=0
    int   prev_yt = yt;
    float prev_m  = fm;
    float C = 0.0f, tv = 0.0f;

    if (j == 0) sh_delta = x;
    __syncthreads();
    float delta = sh_delta;
    C += delta;
    float r = x - delta;
    sh_e[j] = __expf(r);

    // Prefetch t = 1
    float yv_n = yrow[KDIM + j];
    int   yt_n = trow[1];

    for (int t = 1; t < N; ++t) {
        yv = yv_n; yt = yt_n;
        if (t + 1 < N) {                                // prefetch t+1 (hides LDG latency)
            yv_n = yrow[(size_t)(t + 1) * KDIM + j];
            yt_n = trow[t + 1];
        }
        m  = __syncthreads_and(yv > -1000000.0f);       // barrier: sh_e writes visible + mask
        fm = m ? 1.0f : 0.0f;
        float emit = yv * fm;

        // s_j = sum_i exp(r_i) * E[i][j]   (32 packed FFMA2, 4 independent chains)
        unsigned long long a0 = 0ull, a1 = 0ull, a2 = 0ull, a3 = 0ull;
        const float4* ep = (const float4*)sh_e;
#pragma unroll
        for (int k = 0; k < KDIM / 4; ++k) {
            float4 e4 = ep[k];
            unsigned long long e01 = pk2(e4.x, e4.y);
            unsigned long long e23 = pk2(e4.z, e4.w);
            if (k & 1) { a2 = fma2(e01, Ec[2 * k], a2); a3 = fma2(e23, Ec[2 * k + 1], a3); }
            else       { a0 = fma2(e01, Ec[2 * k], a0); a1 = fma2(e23, Ec[2 * k + 1], a1); }
        }
        unsigned long long aa = add2(add2(a0, a1), add2(a2, a3));
        float lo, hi;
        asm("mov.b64 {%0, %1}, %2;" : "=f"(lo), "=f"(hi) : "l"(aa));
        float s = lo + hi;

        float u = __logf(s) + emit;       // new alpha_j - C (if masked in)
        x = m ? u : r;                    // mask: keep old residual when mm == 0

        // target-score accumulation
        point += (j == yt) ? emit : 0.0f;
        if (j == 0) {
            tv += sh_trans[prev_yt * KDIM + yt] * (prev_m * fm);
            sh_delta = x;
        }
        prev_yt = yt; prev_m = fm;

        __syncthreads();                  // sh_delta visible; all dot-reads of sh_e done
        delta = sh_delta;
        C += delta;
        r = x - delta;
        sh_e[j] = __expf(r);              // next iteration's operand
    }

    // ---- epilogue: log_norm - target_score ----
    sh_red[j] = point;
    __syncthreads();                      // sh_e (last exp(r)) + sh_red visible
    if (j == 0) {
        float se = 0.0f, sp = 0.0f;
        for (int i = 0; i < KDIM; ++i) { se += sh_e[i]; sp += sh_red[i]; }
        out[b] = C + logf(se) - (sp + tv);
    }
}

extern "C" void kernel_launch(void* const* d_in, const int* in_sizes, int n_in,
                              void* d_out, int out_size) {
    const float* y_pred = (const float*)d_in[0];   // [B, N, K] f32
    const float* trans  = (const float*)d_in[1];   // [K, K]    f32
    const int*   y_true = (const int*)  d_in[2];   // [B, N]    i32
    float* out = (float*)d_out;                    // [B]       f32

    int B = out_size;                  // 512
    int N = in_sizes[2] / B;           // 1024
    crf_fwd_kernel<<<B, KDIM>>>(y_pred, trans, y_true, out, N);
}

// round 3
// speedup vs baseline: 1.0562x; 1.0562x over previous
#include <cuda_runtime.h>
#include <cuda_bf16.h>

#define KDIM 64
#define LOG2E 1.4426950408889634f
#define LN2   0.6931471805599453f
#define RING  8      // emit ring slots (power of 2)
#define DIST  6      // prefetch distance in steps
#define FRING 4      // mask-flag ring slots

// ---- packed f32x2 helpers (sm_100+) ----
__device__ __forceinline__ unsigned long long pk2(float a, float b) {
    unsigned long long r;
    asm("mov.b64 %0, {%1, %2};" : "=l"(r) : "f"(a), "f"(b));
    return r;
}
__device__ __forceinline__ unsigned long long fma2(unsigned long long a, unsigned long long b,
                                                   unsigned long long c) {
    unsigned long long d;
    asm("fma.rn.f32x2 %0, %1, %2, %3;" : "=l"(d) : "l"(a), "l"(b), "l"(c));
    return d;
}
__device__ __forceinline__ unsigned long long add2(unsigned long long a, unsigned long long b) {
    unsigned long long d;
    asm("add.rn.f32x2 %0, %1, %2;" : "=l"(d) : "l"(a), "l"(b));
    return d;
}
__device__ __forceinline__ float ex2f(float x) {
    float y; asm("ex2.approx.f32 %0, %1;" : "=f"(y) : "f"(x)); return y;
}
__device__ __forceinline__ float lg2f(float x) {
    float y; asm("lg2.approx.f32 %0, %1;" : "=f"(y) : "f"(x)); return y;
}

// One CTA (2 warps, 64 threads) per batch row. Thread j owns state j.
// Stored residual w_j(t): sh_e[buf][j] = 2^(w_j(t)), true alpha2_j(t) = C2(t) + w_j(t).
// Step: w_j(t) = lg2( sum_i E[i][j] * 2^(w_i(t-1)) ) + emit2 - delta,  delta = w_0(t-1),
// C2(t) = C2(t-1) + delta. Since all w share the same frame, the dot's exponents are the
// bounded alpha-spread => w stays bounded (no oscillator, unlike the double-lag scheme).
__global__ __launch_bounds__(KDIM, 4) void crf_fwd_kernel(
    const float* __restrict__ y_pred,   // [B, N, K]
    const float* __restrict__ trans,    // [K, K]
    const int*   __restrict__ y_true,   // [B, N]
    float*       __restrict__ out,      // [B]
    int N)
{
    __shared__ float sh_trans[KDIM * KDIM];
    __shared__ __align__(16) float sh_e[2][KDIM];
    __shared__ float sh_delta[2];
    __shared__ unsigned sh_mand[FRING][2];
    __shared__ float sh_red[KDIM];

    const int j = threadIdx.x;
    const int w = j >> 5;
    const int b = blockIdx.x;

    for (int i = j; i < KDIM * KDIM; i += KDIM) sh_trans[i] = trans[i];
    __syncthreads();

    // Column j of E = exp(trans) (natural exp; recursion runs base-2 on top of it)
    unsigned long long Ec[KDIM / 2];
#pragma unroll
    for (int k = 0; k < KDIM / 2; ++k) {
        float e0 = __expf(sh_trans[(2 * k)     * KDIM + j]);
        float e1 = __expf(sh_trans[(2 * k + 1) * KDIM + j]);
        Ec[k] = pk2(e0, e1);
    }

    const float* yrow = y_pred + (size_t)b * N * KDIM;
    const int*   trow = y_true + (size_t)b * N;

    // ---- t = 0 ----
    float yv0 = yrow[j];
    int   yt0 = trow[0];
    int   m0  = __syncthreads_and(yv0 > -1000000.0f);
    float fm0 = m0 ? 1.0f : 0.0f;
    float x2 = (yv0 * fm0) * LOG2E;          // w_j(0), C2 = 0
    float point = (j == yt0) ? yv0 * fm0 : 0.0f;
    int   prev_yt = yt0;
    float prev_m  = fm0;
    float C2 = 0.0f, tv = 0.0f;
    sh_e[0][j] = ex2f(x2);
    if (j == 0) sh_delta[0] = x2;

    // ---- prime prefetch ring (steps 1..DIST) ----
    float ring[RING];
    int   tring[RING];
#pragma unroll
    for (int p = 1; p <= DIST; ++p) {
        int tt = (p < N) ? p : (N - 1);
        ring[p & (RING - 1)]  = yrow[(size_t)tt * KDIM + j];
        tring[p & (RING - 1)] = trow[tt];
    }
    // mask flags for step 1
    sh_mand[1 & (FRING - 1)][w] = __all_sync(0xffffffffu, ring[1 & (RING - 1)] > -1000000.0f);
    __syncthreads();

    // ---- main loop, unrolled by 8 so all ring indices are compile-time ----
    // invariant: t0 === 1 (mod 8)
    for (int t0 = 1; t0 < N; t0 += 8) {
#pragma unroll
        for (int u = 0; u < 8; ++u) {
            const int t = t0 + u;
            if (t < N) {
                const int buf  = (1 + u) & 1;
                const int pbuf = buf ^ 1;

                float delta = sh_delta[pbuf];                       // w_0(t-1)
                unsigned m = sh_mand[(1 + u) & (FRING - 1)][0]
                           & sh_mand[(1 + u) & (FRING - 1)][1];
                float yv = ring[(1 + u) & (RING - 1)];
                int   yt = tring[(1 + u) & (RING - 1)];

                // mask flags for step t+1 (value prefetched long ago)
                sh_mand[(2 + u) & (FRING - 1)][w] =
                    __all_sync(0xffffffffu, ring[(2 + u) & (RING - 1)] > -1000000.0f);

                // prefetch step t+DIST
                {
                    int tt = (t + DIST < N) ? (t + DIST) : (N - 1);
                    ring[(7 + u) & (RING - 1)]  = yrow[(size_t)tt * KDIM + j];
                    tring[(7 + u) & (RING - 1)] = trow[tt];
                }

                // s_j = sum_i sh_e[pbuf][i] * E[i][j]  (8 chains, depth 4)
                unsigned long long a0 = 0ull, a1 = 0ull, a2 = 0ull, a3 = 0ull;
                unsigned long long a4 = 0ull, a5 = 0ull, a6 = 0ull, a7 = 0ull;
                const float4* ep = (const float4*)sh_e[pbuf];
#pragma unroll
                for (int k = 0; k < KDIM / 4; ++k) {
                    float4 e4 = ep[k];
                    unsigned long long e01 = pk2(e4.x, e4.y);
                    unsigned long long e23 = pk2(e4.z, e4.w);
                    switch (k & 3) {
                        case 0: a0 = fma2(e01, Ec[2 * k], a0); a1 = fma2(e23, Ec[2 * k + 1], a1); break;
                        case 1: a2 = fma2(e01, Ec[2 * k], a2); a3 = fma2(e23, Ec[2 * k + 1], a3); break;
                        case 2: a4 = fma2(e01, Ec[2 * k], a4); a5 = fma2(e23, Ec[2 * k + 1], a5); break;
                        default:a6 = fma2(e01, Ec[2 * k], a6); a7 = fma2(e23, Ec[2 * k + 1], a7); break;
                    }
                }
                unsigned long long aa = add2(add2(add2(a0, a1), add2(a2, a3)),
                                             add2(add2(a4, a5), add2(a6, a7)));
                float lo, hi;
                asm("mov.b64 {%0, %1}, %2;" : "=f"(lo), "=f"(hi) : "l"(aa));
                float s = lo + hi;

                float fm = m ? 1.0f : 0.0f;
                float emit2 = yv * (fm * LOG2E);
                float xnew = lg2f(s) + emit2;         // pre-shift new residual
                // masked-out: alpha frozen => w_new = w_old - delta as well
                x2 = (m ? xnew : x2) - delta;
                C2 += delta;

                point += (j == yt) ? yv * fm : 0.0f;
                if (j == 0) {
                    tv += sh_trans[prev_yt * KDIM + yt] * (prev_m * fm);
                    sh_delta[buf] = x2;               // w_0(t), post-shift
                }
                prev_yt = yt; prev_m = fm;

                sh_e[buf][j] = ex2f(x2);

                __syncthreads();                      // single barrier per step
            }
        }
    }

    // ---- epilogue:  alpha2_i = C2 + w_i ;  sh_e[lastbuf][i] = 2^(w_i) ----
    sh_red[j] = point;
    __syncthreads();
    if (j == 0) {
        const int lastbuf = (N - 1) & 1;
        float se = 0.0f, sp = 0.0f;
        for (int i = 0; i < KDIM; ++i) { se += sh_e[lastbuf][i]; sp += sh_red[i]; }
        float log_norm = LN2 * (C2 + lg2f(se));
        out[b] = log_norm - (sp + tv);
    }
}

extern "C" void kernel_launch(void* const* d_in, const int* in_sizes, int n_in,
                              void* d_out, int out_size) {
    const float* y_pred = (const float*)d_in[0];   // [B, N, K] f32
    const float* trans  = (const float*)d_in[1];   // [K, K]    f32
    const int*   y_true = (const int*)  d_in[2];   // [B, N]    i32
    float* out = (float*)d_out;                    // [B]       f32

    int B = out_size;                  // 512
    int N = in_sizes[2] / B;           // 1024
    crf_fwd_kernel<<<B, KDIM>>>(y_pred, trans, y_true, out, N);
}